// round 6
// baseline (speedup 1.0000x reference)
#include <cuda_runtime.h>
#include <cuda_bf16.h>
#include <math.h>

// ---------------- problem constants ----------------
#define CH 192
#define HEADS 6
#define MTOT 131072
#define HIDDEN 768

// ---------------- scratch ----------------
__device__ __nv_bfloat16 gb_xn  [(size_t)MTOT * CH];
__device__ __nv_bfloat16 gb_qkv [(size_t)MTOT * 3 * CH];
__device__ __nv_bfloat16 gb_attn[(size_t)MTOT * CH];
__device__ float         g_x1   [(size_t)MTOT * CH];
__device__ __nv_bfloat16 gb_h2  [(size_t)MTOT * CH];
__device__ __nv_bfloat16 gb_hid [(size_t)MTOT * HIDDEN];
__device__ __nv_bfloat16 gb_w[576*192 + 192*192 + 768*192 + 192*768];

__device__ __forceinline__ int gather_row(int m) {
    int win = m >> 6, n = m & 63;
    int b   = win >> 10, rem = win & 1023;
    int wh  = rem >> 5,  ww  = rem & 31;
    int r   = n >> 3,    c   = n & 7;
    int hs  = (wh * 8 + r + 4) & 255;
    int ws_ = (ww * 8 + c + 4) & 255;
    return (b << 16) | (hs << 8) | ws_;
}

__device__ __forceinline__ unsigned smem_u32(const void* p) {
    return (unsigned)__cvta_generic_to_shared(p);
}

// ---------------- fp32 -> bf16 convert ----------------
__global__ void f2bf_kernel(const float* __restrict__ in, __nv_bfloat16* __restrict__ out, int n) {
    int i = blockIdx.x * 256 + threadIdx.x;
    if (i < n) out[i] = __float2bfloat16(in[i]);
}

// ---------------- LayerNorm: one warp per row of 192, bf16 out ----------------
__global__ void ln_kernel(const float* __restrict__ in, const float* __restrict__ g,
                          const float* __restrict__ b, __nv_bfloat16* __restrict__ out, int M) {
    int row  = blockIdx.x * (blockDim.x >> 5) + (threadIdx.x >> 5);
    int lane = threadIdx.x & 31;
    if (row >= M) return;
    const float* rp = in + (size_t)row * CH;
    float v[6];
    float s = 0.f;
#pragma unroll
    for (int i = 0; i < 6; i++) { v[i] = rp[lane + 32 * i]; s += v[i]; }
#pragma unroll
    for (int o = 16; o; o >>= 1) s += __shfl_xor_sync(0xffffffffu, s, o);
    float mean = s * (1.f / 192.f);
    float q = 0.f;
#pragma unroll
    for (int i = 0; i < 6; i++) { float d = v[i] - mean; q += d * d; }
#pragma unroll
    for (int o = 16; o; o >>= 1) q += __shfl_xor_sync(0xffffffffu, q, o);
    float inv = rsqrtf(q * (1.f / 192.f) + 1e-5f);
    __nv_bfloat16* op = out + (size_t)row * CH;
#pragma unroll
    for (int i = 0; i < 6; i++) {
        int col = lane + 32 * i;
        op[col] = __float2bfloat16((v[i] - mean) * inv * g[col] + b[col]);
    }
}

// ---------------- HMMA bf16 GEMM, 128x128 tile, k-step 48, 3-stage cp.async ----------------
// C[m,n] = sum_k A[m,k] * W[n,k]
// EPI: 0 = store bf16; 1 = +bias, exact GELU, bf16; 2 = scatter row, +res[gathered], fp32; 3 = +bias, +res[m], fp32
#define KSTEP 48
#define SPAD 56      // 48 + 8 pad; 112B row stride -> ldmatrix phase conflict-free
#define STAGE_ELEMS (128 * SPAD)
#define GSMEM_BYTES (3 * STAGE_ELEMS * 2 * 2)   // 3 stages, A+B, bf16 = 86016

template<int EPI, bool GATHER>
__global__ void __launch_bounds__(256, 2) gemm_mma(
    const __nv_bfloat16* __restrict__ A, const __nv_bfloat16* __restrict__ W,
    const float* __restrict__ bias, const float* __restrict__ res,
    void* __restrict__ Cout, int K, int N)
{
    extern __shared__ __nv_bfloat16 dsm[];
    __nv_bfloat16* AsB = dsm;                      // [3][128][SPAD]
    __nv_bfloat16* BsB = dsm + 3 * STAGE_ELEMS;    // [3][128][SPAD]

    const int m0 = blockIdx.x * 128, n0 = blockIdx.y * 128;
    const int t = threadIdx.x, lane = t & 31, wid = t >> 5;
    const int wm = wid & 1, wn = wid >> 1;   // 2(M) x 4(N) warps, each 64x32

    // gmem->smem: thread t loads row t>>1, 3 x 16B chunks at col (t&1)*24 + c*8
    const int lr = t >> 1;
    const int lc = (t & 1) * 24;
    const int arow = GATHER ? gather_row(m0 + lr) : (m0 + lr);
    const __nv_bfloat16* Ap = A + (size_t)arow * K + lc;
    int bg = n0 + lr; if (bg >= N) bg = 0;
    const __nv_bfloat16* Wp = W + (size_t)bg * K + lc;

    float acc[4][4][4];
#pragma unroll
    for (int i = 0; i < 4; i++)
#pragma unroll
        for (int j = 0; j < 4; j++)
#pragma unroll
            for (int q = 0; q < 4; q++) acc[i][j][q] = 0.f;

    const int nk = K / KSTEP;   // 4 (K=192) or 16 (K=768)

#define LOAD_STAGE(st, ks)                                                                  \
    do {                                                                                    \
        unsigned _da = smem_u32(AsB + (st) * STAGE_ELEMS + lr * SPAD + lc);                 \
        unsigned _db = smem_u32(BsB + (st) * STAGE_ELEMS + lr * SPAD + lc);                 \
        const __nv_bfloat16* _pa = Ap + (ks) * KSTEP;                                       \
        const __nv_bfloat16* _pb = Wp + (ks) * KSTEP;                                       \
        asm volatile("cp.async.cg.shared.global [%0], [%1], 16;\n" :: "r"(_da),      "l"(_pa));      \
        asm volatile("cp.async.cg.shared.global [%0], [%1], 16;\n" :: "r"(_da + 16), "l"(_pa + 8));  \
        asm volatile("cp.async.cg.shared.global [%0], [%1], 16;\n" :: "r"(_da + 32), "l"(_pa + 16)); \
        asm volatile("cp.async.cg.shared.global [%0], [%1], 16;\n" :: "r"(_db),      "l"(_pb));      \
        asm volatile("cp.async.cg.shared.global [%0], [%1], 16;\n" :: "r"(_db + 16), "l"(_pb + 8));  \
        asm volatile("cp.async.cg.shared.global [%0], [%1], 16;\n" :: "r"(_db + 32), "l"(_pb + 16)); \
        asm volatile("cp.async.commit_group;\n");                                           \
    } while (0)

    LOAD_STAGE(0, 0);
    LOAD_STAGE(1, 1);

    const int r16 = lane & 15, chh = lane >> 4;

    for (int ks = 0; ks < nk; ks++) {
        if (ks + 1 < nk) asm volatile("cp.async.wait_group 1;\n");
        else             asm volatile("cp.async.wait_group 0;\n");
        __syncthreads();

        if (ks + 2 < nk) {
            int st = (ks + 2) % 3;
            LOAD_STAGE(st, ks + 2);
        }

        const int buf = ks % 3;
        const __nv_bfloat16* As = AsB + buf * STAGE_ELEMS;
        const __nv_bfloat16* Bs = BsB + buf * STAGE_ELEMS;
#pragma unroll
        for (int kk = 0; kk < 3; kk++) {
            unsigned a[4][4], b[2][4];
#pragma unroll
            for (int i = 0; i < 4; i++) {
                unsigned addr = smem_u32(As + (wm * 64 + i * 16 + r16) * SPAD + kk * 16 + chh * 8);
                asm volatile("ldmatrix.sync.aligned.m8n8.x4.shared.b16 {%0,%1,%2,%3}, [%4];"
                    : "=r"(a[i][0]), "=r"(a[i][1]), "=r"(a[i][2]), "=r"(a[i][3]) : "r"(addr));
            }
#pragma unroll
            for (int j2 = 0; j2 < 2; j2++) {
                unsigned addr = smem_u32(Bs + (wn * 32 + j2 * 16 + r16) * SPAD + kk * 16 + chh * 8);
                asm volatile("ldmatrix.sync.aligned.m8n8.x4.shared.b16 {%0,%1,%2,%3}, [%4];"
                    : "=r"(b[j2][0]), "=r"(b[j2][1]), "=r"(b[j2][2]), "=r"(b[j2][3]) : "r"(addr));
            }
#pragma unroll
            for (int i = 0; i < 4; i++)
#pragma unroll
                for (int j = 0; j < 4; j++) {
                    unsigned b0 = b[j >> 1][j & 1], b1 = b[j >> 1][(j & 1) + 2];
                    asm volatile(
                        "mma.sync.aligned.m16n8k16.row.col.f32.bf16.bf16.f32 "
                        "{%0,%1,%2,%3}, {%4,%5,%6,%7}, {%8,%9}, {%0,%1,%2,%3};"
                        : "+f"(acc[i][j][0]), "+f"(acc[i][j][1]), "+f"(acc[i][j][2]), "+f"(acc[i][j][3])
                        : "r"(a[i][0]), "r"(a[i][1]), "r"(a[i][2]), "r"(a[i][3]), "r"(b0), "r"(b1));
                }
        }
    }
#undef LOAD_STAGE

    // epilogue
#pragma unroll
    for (int i = 0; i < 4; i++) {
        int rbase = m0 + wm * 64 + i * 16 + (lane >> 2);
#pragma unroll
        for (int j = 0; j < 4; j++) {
            int c = n0 + wn * 32 + j * 8 + (lane & 3) * 2;
            if (c < N) {
#pragma unroll
                for (int h = 0; h < 2; h++) {
                    int r = rbase + h * 8;
                    float v0 = acc[i][j][h * 2 + 0];
                    float v1 = acc[i][j][h * 2 + 1];
                    if (bias) { v0 += __ldg(&bias[c]); v1 += __ldg(&bias[c + 1]); }
                    if (EPI == 1) {
                        v0 = 0.5f * v0 * (1.f + erff(v0 * 0.70710678118654752f));
                        v1 = 0.5f * v1 * (1.f + erff(v1 * 0.70710678118654752f));
                    }
                    if (EPI >= 2) {
                        int orow = (EPI == 2) ? gather_row(r) : r;
                        size_t off = (size_t)orow * N + c;
                        float2 rv = *(const float2*)(res + off);
                        float2 ov; ov.x = v0 + rv.x; ov.y = v1 + rv.y;
                        *(float2*)((float*)Cout + off) = ov;
                    } else {
                        __nv_bfloat162 p;
                        p.x = __float2bfloat16(v0); p.y = __float2bfloat16(v1);
                        *(__nv_bfloat162*)((__nv_bfloat16*)Cout + (size_t)r * N + c) = p;
                    }
                }
            }
        }
    }
}

// ---------------- windowed attention: scores in registers ----------------
__device__ __forceinline__ int region(int p) { return p < 248 ? 0 : (p < 252 ? 1 : 2); }

__global__ void __launch_bounds__(64) attn_kernel(const __nv_bfloat16* __restrict__ qkv,
                                                  const float* __restrict__ rpb,
                                                  __nv_bfloat16* __restrict__ out) {
    __shared__ float sk[64][32];
    __shared__ float sv[64][32];
    __shared__ float srpb[225];

    const int win = blockIdx.x;
    const int h   = blockIdx.y;
    const int n   = threadIdx.x;

    for (int i = n; i < 225; i += 64) srpb[i] = rpb[i * HEADS + h];

    const size_t base = (size_t)(win * 64 + n) * (3 * CH) + h * 32;
    const float scale = 0.17677669529663687f;

    float q[32];
    {
        const __nv_bfloat162* qp = (const __nv_bfloat162*)(qkv + base);
        const __nv_bfloat162* kp = (const __nv_bfloat162*)(qkv + base + CH);
        const __nv_bfloat162* vp = (const __nv_bfloat162*)(qkv + base + 2 * CH);
#pragma unroll
        for (int i = 0; i < 16; i++) {
            float2 fq = __bfloat1622float2(qp[i]);
            float2 fk = __bfloat1622float2(kp[i]);
            float2 fv = __bfloat1622float2(vp[i]);
            q[2 * i] = fq.x * scale; q[2 * i + 1] = fq.y * scale;
            sk[n][2 * i] = fk.x; sk[n][2 * i + 1] = fk.y;
            sv[n][2 * i] = fv.x; sv[n][2 * i + 1] = fv.y;
        }
    }
    __syncthreads();

    const int rem = win & 1023;
    const int wh = rem >> 5, ww = rem & 31;
    const int ri = n >> 3, ci = n & 7;
    const int idi = region(wh * 8 + ri) * 3 + region(ww * 8 + ci);

    float s[64];     // scores live in registers
    float mx = -1e30f;
#pragma unroll 4
    for (int j = 0; j < 64; j++) {
        float a = 0.f;
#pragma unroll
        for (int d4 = 0; d4 < 8; d4++) {
            float4 kv = *(const float4*)&sk[j][d4 * 4];
            a = fmaf(q[d4 * 4 + 0], kv.x, a);
            a = fmaf(q[d4 * 4 + 1], kv.y, a);
            a = fmaf(q[d4 * 4 + 2], kv.z, a);
            a = fmaf(q[d4 * 4 + 3], kv.w, a);
        }
        int rj = j >> 3, cj = j & 7;
        a += srpb[(ri - rj + 7) * 15 + (ci - cj + 7)];
        int idj = region(wh * 8 + rj) * 3 + region(ww * 8 + cj);
        if (idi != idj) a -= 100.f;
        s[j] = a;
        mx = fmaxf(mx, a);
    }

    float sum = 0.f;
#pragma unroll
    for (int j = 0; j < 64; j++) {
        float e = __expf(s[j] - mx);
        s[j] = e;
        sum += e;
    }
    float inv = 1.f / sum;

    float o[32];
#pragma unroll
    for (int d = 0; d < 32; d++) o[d] = 0.f;
#pragma unroll 4
    for (int j = 0; j < 64; j++) {
        float p = s[j];
#pragma unroll
        for (int d4 = 0; d4 < 8; d4++) {
            float4 vv = *(const float4*)&sv[j][d4 * 4];
            o[d4 * 4 + 0] = fmaf(p, vv.x, o[d4 * 4 + 0]);
            o[d4 * 4 + 1] = fmaf(p, vv.y, o[d4 * 4 + 1]);
            o[d4 * 4 + 2] = fmaf(p, vv.z, o[d4 * 4 + 2]);
            o[d4 * 4 + 3] = fmaf(p, vv.w, o[d4 * 4 + 3]);
        }
    }

    __nv_bfloat16* op = out + (size_t)(win * 64 + n) * CH + h * 32;
#pragma unroll
    for (int d2 = 0; d2 < 16; d2++) {
        __nv_bfloat162 p;
        p.x = __float2bfloat16(o[2 * d2] * inv);
        p.y = __float2bfloat16(o[2 * d2 + 1] * inv);
        *(__nv_bfloat162*)&op[2 * d2] = p;
    }
}

// ---------------- launcher ----------------
extern "C" void kernel_launch(void* const* d_in, const int* in_sizes, int n_in,
                              void* d_out, int out_size) {
    const float* x       = (const float*)d_in[0];
    const float* norm1_g = (const float*)d_in[1];
    const float* norm1_b = (const float*)d_in[2];
    const float* qkv_w   = (const float*)d_in[3];
    const float* rpb     = (const float*)d_in[4];
    const float* proj_w  = (const float*)d_in[5];
    const float* proj_b  = (const float*)d_in[6];
    const float* norm2_g = (const float*)d_in[7];
    const float* norm2_b = (const float*)d_in[8];
    const float* mlp_w1  = (const float*)d_in[9];
    const float* mlp_b1  = (const float*)d_in[10];
    const float* mlp_w2  = (const float*)d_in[11];
    const float* mlp_b2  = (const float*)d_in[12];
    float* out = (float*)d_out;

    __nv_bfloat16 *xn, *qkvb, *attnb, *h2, *hid, *wbuf;
    float* x1;
    cudaGetSymbolAddress((void**)&xn,    gb_xn);
    cudaGetSymbolAddress((void**)&qkvb,  gb_qkv);
    cudaGetSymbolAddress((void**)&attnb, gb_attn);
    cudaGetSymbolAddress((void**)&x1,    g_x1);
    cudaGetSymbolAddress((void**)&h2,    gb_h2);
    cudaGetSymbolAddress((void**)&hid,   gb_hid);
    cudaGetSymbolAddress((void**)&wbuf,  gb_w);

    __nv_bfloat16* wq = wbuf;
    __nv_bfloat16* wp = wbuf + 576 * 192;
    __nv_bfloat16* w1 = wp   + 192 * 192;
    __nv_bfloat16* w2 = w1   + 768 * 192;

    cudaFuncSetAttribute(gemm_mma<0, true >, cudaFuncAttributeMaxDynamicSharedMemorySize, GSMEM_BYTES);
    cudaFuncSetAttribute(gemm_mma<2, false>, cudaFuncAttributeMaxDynamicSharedMemorySize, GSMEM_BYTES);
    cudaFuncSetAttribute(gemm_mma<1, false>, cudaFuncAttributeMaxDynamicSharedMemorySize, GSMEM_BYTES);
    cudaFuncSetAttribute(gemm_mma<3, false>, cudaFuncAttributeMaxDynamicSharedMemorySize, GSMEM_BYTES);

    const int M = MTOT;
    const int LN_BLOCKS = M / 8;

    f2bf_kernel<<<(576 * 192 + 255) / 256, 256>>>(qkv_w,  wq, 576 * 192);
    f2bf_kernel<<<(192 * 192 + 255) / 256, 256>>>(proj_w, wp, 192 * 192);
    f2bf_kernel<<<(768 * 192 + 255) / 256, 256>>>(mlp_w1, w1, 768 * 192);
    f2bf_kernel<<<(192 * 768 + 255) / 256, 256>>>(mlp_w2, w2, 192 * 768);

    ln_kernel<<<LN_BLOCKS, 256>>>(x, norm1_g, norm1_b, xn, M);

    gemm_mma<0, true><<<dim3(M / 128, 5), 256, GSMEM_BYTES>>>(
        xn, wq, nullptr, nullptr, qkvb, CH, 3 * CH);

    attn_kernel<<<dim3(2048, HEADS), 64>>>(qkvb, rpb, attnb);

    gemm_mma<2, false><<<dim3(M / 128, 2), 256, GSMEM_BYTES>>>(
        attnb, wp, proj_b, x, x1, CH, CH);

    ln_kernel<<<LN_BLOCKS, 256>>>(x1, norm2_g, norm2_b, h2, M);

    gemm_mma<1, false><<<dim3(M / 128, 6), 256, GSMEM_BYTES>>>(
        h2, w1, mlp_b1, nullptr, hid, CH, HIDDEN);

    gemm_mma<3, false><<<dim3(M / 128, 2), 256, GSMEM_BYTES>>>(
        hid, w2, mlp_b2, x1, out, HIDDEN, CH);
}

// round 7
// speedup vs baseline: 1.5300x; 1.5300x over previous
#include <cuda_runtime.h>
#include <cuda_bf16.h>
#include <math.h>

// ---------------- problem constants ----------------
#define CH 192
#define HEADS 6
#define MTOT 131072
#define HIDDEN 768

// ---------------- scratch ----------------
__device__ __nv_bfloat16 gb_xn  [(size_t)MTOT * CH];
__device__ __nv_bfloat16 gb_qkv [(size_t)MTOT * 3 * CH];
__device__ __nv_bfloat16 gb_attn[(size_t)MTOT * CH];
__device__ float         g_x1   [(size_t)MTOT * CH];
__device__ __nv_bfloat16 gb_h2  [(size_t)MTOT * CH];
__device__ __nv_bfloat16 gb_hid [(size_t)MTOT * HIDDEN];
__device__ __nv_bfloat16 gb_w[576*192 + 192*192 + 768*192 + 192*768];

__device__ __forceinline__ int gather_row(int m) {
    int win = m >> 6, n = m & 63;
    int b   = win >> 10, rem = win & 1023;
    int wh  = rem >> 5,  ww  = rem & 31;
    int r   = n >> 3,    c   = n & 7;
    int hs  = (wh * 8 + r + 4) & 255;
    int ws_ = (ww * 8 + c + 4) & 255;
    return (b << 16) | (hs << 8) | ws_;
}

__device__ __forceinline__ unsigned smem_u32(const void* p) {
    return (unsigned)__cvta_generic_to_shared(p);
}

// ---------------- all weights fp32 -> bf16, ONE launch (also steers ncu skip onto GEMM) ----------------
#define WQ_SZ  110592   // 576*192
#define WP_SZ  36864    // 192*192
#define W1_SZ  147456   // 768*192
#define W2_SZ  147456   // 192*768
#define WTOT   (WQ_SZ + WP_SZ + W1_SZ + W2_SZ)

__global__ void wconv_all(const float* __restrict__ qkv_w, const float* __restrict__ proj_w,
                          const float* __restrict__ w1,    const float* __restrict__ w2,
                          __nv_bfloat16* __restrict__ out) {
    int i = blockIdx.x * 256 + threadIdx.x;
    if (i >= WTOT) return;
    const float* src; int off;
    if (i < WQ_SZ)                 { src = qkv_w;  off = i; }
    else if (i < WQ_SZ + WP_SZ)    { src = proj_w; off = i - WQ_SZ; }
    else if (i < WQ_SZ + WP_SZ + W1_SZ) { src = w1; off = i - WQ_SZ - WP_SZ; }
    else                           { src = w2;     off = i - WQ_SZ - WP_SZ - W1_SZ; }
    out[i] = __float2bfloat16(src[off]);
}

// ---------------- LayerNorm: one warp per row of 192, bf16 out ----------------
__global__ void ln_kernel(const float* __restrict__ in, const float* __restrict__ g,
                          const float* __restrict__ b, __nv_bfloat16* __restrict__ out, int M) {
    int row  = blockIdx.x * (blockDim.x >> 5) + (threadIdx.x >> 5);
    int lane = threadIdx.x & 31;
    if (row >= M) return;
    const float* rp = in + (size_t)row * CH;
    float v[6];
    float s = 0.f;
#pragma unroll
    for (int i = 0; i < 6; i++) { v[i] = rp[lane + 32 * i]; s += v[i]; }
#pragma unroll
    for (int o = 16; o; o >>= 1) s += __shfl_xor_sync(0xffffffffu, s, o);
    float mean = s * (1.f / 192.f);
    float q = 0.f;
#pragma unroll
    for (int i = 0; i < 6; i++) { float d = v[i] - mean; q += d * d; }
#pragma unroll
    for (int o = 16; o; o >>= 1) q += __shfl_xor_sync(0xffffffffu, q, o);
    float inv = rsqrtf(q * (1.f / 192.f) + 1e-5f);
    __nv_bfloat16* op = out + (size_t)row * CH;
#pragma unroll
    for (int i = 0; i < 6; i++) {
        int col = lane + 32 * i;
        op[col] = __float2bfloat16((v[i] - mean) * inv * g[col] + b[col]);
    }
}

// ---------------- HMMA bf16 GEMM, 128x128 tile, k-step 32, 3-stage cp.async (R3-exact) ----------------
// C[m,n] = sum_k A[m,k] * W[n,k]
// EPI: 0 = store bf16; 1 = +bias, exact GELU, bf16; 2 = scatter row, +res[gathered], fp32; 3 = +bias, +res[m], fp32
#define KSTEP 32
#define SPAD 40   // 32 + 8 pad (80B row stride: 16B aligned, ldmatrix conflict-free)

template<int EPI, bool GATHER>
__global__ void __launch_bounds__(256) gemm_mma(
    const __nv_bfloat16* __restrict__ A, const __nv_bfloat16* __restrict__ W,
    const float* __restrict__ bias, const float* __restrict__ res,
    void* __restrict__ Cout, int K, int N)
{
    __shared__ __nv_bfloat16 As[3][128][SPAD];
    __shared__ __nv_bfloat16 Bs[3][128][SPAD];
    const int m0 = blockIdx.x * 128, n0 = blockIdx.y * 128;
    const int t = threadIdx.x, lane = t & 31, wid = t >> 5;
    const int wm = wid & 1, wn = wid >> 1;   // 2 (M) x 4 (N) warps, each 64x32

    const int lr = t >> 2;              // 0..63
    const int lch = (t & 3) * 8;        // k-offset within stage (elements)
    const int ar0 = GATHER ? gather_row(m0 + lr)      : (m0 + lr);
    const int ar1 = GATHER ? gather_row(m0 + 64 + lr) : (m0 + 64 + lr);
    const __nv_bfloat16* Ap0 = A + (size_t)ar0 * K + lch;
    const __nv_bfloat16* Ap1 = A + (size_t)ar1 * K + lch;
    int bg0 = n0 + lr;      if (bg0 >= N) bg0 = 0;
    int bg1 = n0 + 64 + lr; if (bg1 >= N) bg1 = 0;
    const __nv_bfloat16* Wp0 = W + (size_t)bg0 * K + lch;
    const __nv_bfloat16* Wp1 = W + (size_t)bg1 * K + lch;

    float acc[4][4][4];
#pragma unroll
    for (int i = 0; i < 4; i++)
#pragma unroll
        for (int j = 0; j < 4; j++)
#pragma unroll
            for (int q = 0; q < 4; q++) acc[i][j][q] = 0.f;

    const int nk = K / KSTEP;   // 6 (K=192) or 24 (K=768)

#define LOAD_STAGE(st, ks)                                                              \
    do {                                                                                \
        unsigned _a0 = smem_u32(&As[st][lr][lch]);                                      \
        unsigned _a1 = smem_u32(&As[st][64 + lr][lch]);                                 \
        unsigned _b0 = smem_u32(&Bs[st][lr][lch]);                                      \
        unsigned _b1 = smem_u32(&Bs[st][64 + lr][lch]);                                 \
        asm volatile("cp.async.cg.shared.global [%0], [%1], 16;\n" :: "r"(_a0), "l"(Ap0 + (ks) * KSTEP)); \
        asm volatile("cp.async.cg.shared.global [%0], [%1], 16;\n" :: "r"(_a1), "l"(Ap1 + (ks) * KSTEP)); \
        asm volatile("cp.async.cg.shared.global [%0], [%1], 16;\n" :: "r"(_b0), "l"(Wp0 + (ks) * KSTEP)); \
        asm volatile("cp.async.cg.shared.global [%0], [%1], 16;\n" :: "r"(_b1), "l"(Wp1 + (ks) * KSTEP)); \
        asm volatile("cp.async.commit_group;\n");                                       \
    } while (0)

    LOAD_STAGE(0, 0);
    LOAD_STAGE(1, 1);

    const int r16 = lane & 15, chh = lane >> 4;

    for (int ks = 0; ks < nk; ks++) {
        if (ks + 1 < nk) asm volatile("cp.async.wait_group 1;\n");
        else             asm volatile("cp.async.wait_group 0;\n");
        __syncthreads();

        if (ks + 2 < nk) {
            int st = (ks + 2) % 3;
            LOAD_STAGE(st, ks + 2);
        }

        const int buf = ks % 3;
#pragma unroll
        for (int kk = 0; kk < 2; kk++) {
            unsigned a[4][4], b[2][4];
#pragma unroll
            for (int i = 0; i < 4; i++) {
                unsigned addr = smem_u32(&As[buf][wm * 64 + i * 16 + r16][kk * 16 + chh * 8]);
                asm volatile("ldmatrix.sync.aligned.m8n8.x4.shared.b16 {%0,%1,%2,%3}, [%4];"
                    : "=r"(a[i][0]), "=r"(a[i][1]), "=r"(a[i][2]), "=r"(a[i][3]) : "r"(addr));
            }
#pragma unroll
            for (int j2 = 0; j2 < 2; j2++) {
                unsigned addr = smem_u32(&Bs[buf][wn * 32 + j2 * 16 + r16][kk * 16 + chh * 8]);
                asm volatile("ldmatrix.sync.aligned.m8n8.x4.shared.b16 {%0,%1,%2,%3}, [%4];"
                    : "=r"(b[j2][0]), "=r"(b[j2][1]), "=r"(b[j2][2]), "=r"(b[j2][3]) : "r"(addr));
            }
#pragma unroll
            for (int i = 0; i < 4; i++)
#pragma unroll
                for (int j = 0; j < 4; j++) {
                    unsigned b0 = b[j >> 1][j & 1], b1 = b[j >> 1][(j & 1) + 2];
                    asm volatile(
                        "mma.sync.aligned.m16n8k16.row.col.f32.bf16.bf16.f32 "
                        "{%0,%1,%2,%3}, {%4,%5,%6,%7}, {%8,%9}, {%0,%1,%2,%3};"
                        : "+f"(acc[i][j][0]), "+f"(acc[i][j][1]), "+f"(acc[i][j][2]), "+f"(acc[i][j][3])
                        : "r"(a[i][0]), "r"(a[i][1]), "r"(a[i][2]), "r"(a[i][3]), "r"(b0), "r"(b1));
                }
        }
    }
#undef LOAD_STAGE

    // epilogue
#pragma unroll
    for (int i = 0; i < 4; i++) {
        int rbase = m0 + wm * 64 + i * 16 + (lane >> 2);
#pragma unroll
        for (int j = 0; j < 4; j++) {
            int c = n0 + wn * 32 + j * 8 + (lane & 3) * 2;
            if (c < N) {
#pragma unroll
                for (int h = 0; h < 2; h++) {
                    int r = rbase + h * 8;
                    float v0 = acc[i][j][h * 2 + 0];
                    float v1 = acc[i][j][h * 2 + 1];
                    if (bias) { v0 += __ldg(&bias[c]); v1 += __ldg(&bias[c + 1]); }
                    if (EPI == 1) {
                        v0 = 0.5f * v0 * (1.f + erff(v0 * 0.70710678118654752f));
                        v1 = 0.5f * v1 * (1.f + erff(v1 * 0.70710678118654752f));
                    }
                    if (EPI >= 2) {
                        int orow = (EPI == 2) ? gather_row(r) : r;
                        size_t off = (size_t)orow * N + c;
                        float2 rv = *(const float2*)(res + off);
                        float2 ov; ov.x = v0 + rv.x; ov.y = v1 + rv.y;
                        *(float2*)((float*)Cout + off) = ov;
                    } else {
                        __nv_bfloat162 p;
                        p.x = __float2bfloat16(v0); p.y = __float2bfloat16(v1);
                        *(__nv_bfloat162*)((__nv_bfloat16*)Cout + (size_t)r * N + c) = p;
                    }
                }
            }
        }
    }
}

// ---------------- windowed attention: scores in registers ----------------
__device__ __forceinline__ int region(int p) { return p < 248 ? 0 : (p < 252 ? 1 : 2); }

__global__ void __launch_bounds__(64) attn_kernel(const __nv_bfloat16* __restrict__ qkv,
                                                  const float* __restrict__ rpb,
                                                  __nv_bfloat16* __restrict__ out) {
    __shared__ float sk[64][32];
    __shared__ float sv[64][32];
    __shared__ float srpb[225];

    const int win = blockIdx.x;
    const int h   = blockIdx.y;
    const int n   = threadIdx.x;

    for (int i = n; i < 225; i += 64) srpb[i] = rpb[i * HEADS + h];

    const size_t base = (size_t)(win * 64 + n) * (3 * CH) + h * 32;
    const float scale = 0.17677669529663687f;

    float q[32];
    {
        const __nv_bfloat162* qp = (const __nv_bfloat162*)(qkv + base);
        const __nv_bfloat162* kp = (const __nv_bfloat162*)(qkv + base + CH);
        const __nv_bfloat162* vp = (const __nv_bfloat162*)(qkv + base + 2 * CH);
#pragma unroll
        for (int i = 0; i < 16; i++) {
            float2 fq = __bfloat1622float2(qp[i]);
            float2 fk = __bfloat1622float2(kp[i]);
            float2 fv = __bfloat1622float2(vp[i]);
            q[2 * i] = fq.x * scale; q[2 * i + 1] = fq.y * scale;
            sk[n][2 * i] = fk.x; sk[n][2 * i + 1] = fk.y;
            sv[n][2 * i] = fv.x; sv[n][2 * i + 1] = fv.y;
        }
    }
    __syncthreads();

    const int rem = win & 1023;
    const int wh = rem >> 5, ww = rem & 31;
    const int ri = n >> 3, ci = n & 7;
    const int idi = region(wh * 8 + ri) * 3 + region(ww * 8 + ci);

    float s[64];
    float mx = -1e30f;
#pragma unroll 4
    for (int j = 0; j < 64; j++) {
        float a = 0.f;
#pragma unroll
        for (int d4 = 0; d4 < 8; d4++) {
            float4 kv = *(const float4*)&sk[j][d4 * 4];
            a = fmaf(q[d4 * 4 + 0], kv.x, a);
            a = fmaf(q[d4 * 4 + 1], kv.y, a);
            a = fmaf(q[d4 * 4 + 2], kv.z, a);
            a = fmaf(q[d4 * 4 + 3], kv.w, a);
        }
        int rj = j >> 3, cj = j & 7;
        a += srpb[(ri - rj + 7) * 15 + (ci - cj + 7)];
        int idj = region(wh * 8 + rj) * 3 + region(ww * 8 + cj);
        if (idi != idj) a -= 100.f;
        s[j] = a;
        mx = fmaxf(mx, a);
    }

    float sum = 0.f;
#pragma unroll
    for (int j = 0; j < 64; j++) {
        float e = __expf(s[j] - mx);
        s[j] = e;
        sum += e;
    }
    float inv = 1.f / sum;

    float o[32];
#pragma unroll
    for (int d = 0; d < 32; d++) o[d] = 0.f;
#pragma unroll 4
    for (int j = 0; j < 64; j++) {
        float p = s[j];
#pragma unroll
        for (int d4 = 0; d4 < 8; d4++) {
            float4 vv = *(const float4*)&sv[j][d4 * 4];
            o[d4 * 4 + 0] = fmaf(p, vv.x, o[d4 * 4 + 0]);
            o[d4 * 4 + 1] = fmaf(p, vv.y, o[d4 * 4 + 1]);
            o[d4 * 4 + 2] = fmaf(p, vv.z, o[d4 * 4 + 2]);
            o[d4 * 4 + 3] = fmaf(p, vv.w, o[d4 * 4 + 3]);
        }
    }

    __nv_bfloat16* op = out + (size_t)(win * 64 + n) * CH + h * 32;
#pragma unroll
    for (int d2 = 0; d2 < 16; d2++) {
        __nv_bfloat162 p;
        p.x = __float2bfloat16(o[2 * d2] * inv);
        p.y = __float2bfloat16(o[2 * d2 + 1] * inv);
        *(__nv_bfloat162*)&op[2 * d2] = p;
    }
}

// ---------------- launcher ----------------
extern "C" void kernel_launch(void* const* d_in, const int* in_sizes, int n_in,
                              void* d_out, int out_size) {
    const float* x       = (const float*)d_in[0];
    const float* norm1_g = (const float*)d_in[1];
    const float* norm1_b = (const float*)d_in[2];
    const float* qkv_w   = (const float*)d_in[3];
    const float* rpb     = (const float*)d_in[4];
    const float* proj_w  = (const float*)d_in[5];
    const float* proj_b  = (const float*)d_in[6];
    const float* norm2_g = (const float*)d_in[7];
    const float* norm2_b = (const float*)d_in[8];
    const float* mlp_w1  = (const float*)d_in[9];
    const float* mlp_b1  = (const float*)d_in[10];
    const float* mlp_w2  = (const float*)d_in[11];
    const float* mlp_b2  = (const float*)d_in[12];
    float* out = (float*)d_out;

    __nv_bfloat16 *xn, *qkvb, *attnb, *h2, *hid, *wbuf;
    float* x1;
    cudaGetSymbolAddress((void**)&xn,    gb_xn);
    cudaGetSymbolAddress((void**)&qkvb,  gb_qkv);
    cudaGetSymbolAddress((void**)&attnb, gb_attn);
    cudaGetSymbolAddress((void**)&x1,    g_x1);
    cudaGetSymbolAddress((void**)&h2,    gb_h2);
    cudaGetSymbolAddress((void**)&hid,   gb_hid);
    cudaGetSymbolAddress((void**)&wbuf,  gb_w);

    __nv_bfloat16* wq = wbuf;
    __nv_bfloat16* wp = wbuf + WQ_SZ;
    __nv_bfloat16* w1 = wp   + WP_SZ;
    __nv_bfloat16* w2 = w1   + W1_SZ;

    const int M = MTOT;
    const int LN_BLOCKS = M / 8;

    // 0: all weight conversions in one launch
    wconv_all<<<(WTOT + 255) / 256, 256>>>(qkv_w, proj_w, mlp_w1, mlp_w2, wbuf);

    // 1: LN1 -> bf16
    ln_kernel<<<LN_BLOCKS, 256>>>(x, norm1_g, norm1_b, xn, M);

    // 2: QKV GEMM (gathered rows = shift + window partition), N = 576
    gemm_mma<0, true><<<dim3(M / 128, 5), 256>>>(xn, wq, nullptr, nullptr, qkvb, CH, 3 * CH);

    // 3: windowed attention
    attn_kernel<<<dim3(2048, HEADS), 64>>>(qkvb, rpb, attnb);

    // 4: proj + scatter + residual -> x1 (fp32)
    gemm_mma<2, false><<<dim3(M / 128, 2), 256>>>(attnb, wp, proj_b, x, x1, CH, CH);

    // 5: LN2 -> bf16
    ln_kernel<<<LN_BLOCKS, 256>>>(x1, norm2_g, norm2_b, h2, M);

    // 6: MLP1 (bias + exact GELU) -> bf16, N = 768
    gemm_mma<1, false><<<dim3(M / 128, 6), 256>>>(h2, w1, mlp_b1, nullptr, hid, CH, HIDDEN);

    // 7: MLP2 (bias + residual) -> fp32 output
    gemm_mma<3, false><<<dim3(M / 128, 2), 256>>>(hid, w2, mlp_b2, x1, out, HIDDEN, CH);
}

// round 8
// speedup vs baseline: 1.6135x; 1.0546x over previous
#include <cuda_runtime.h>
#include <cuda_bf16.h>
#include <math.h>

// ---------------- problem constants ----------------
#define CH 192
#define HEADS 6
#define MTOT 131072
#define HIDDEN 768

// ---------------- scratch ----------------
__device__ __nv_bfloat16 gb_xn  [(size_t)MTOT * CH];
__device__ __nv_bfloat16 gb_qkv [(size_t)MTOT * 3 * CH];
__device__ __nv_bfloat16 gb_attn[(size_t)MTOT * CH];
__device__ float         g_x1   [(size_t)MTOT * CH];
__device__ __nv_bfloat16 gb_h2  [(size_t)MTOT * CH];
__device__ __nv_bfloat16 gb_hid [(size_t)MTOT * HIDDEN];
__device__ __nv_bfloat16 gb_w[576*192 + 192*192 + 768*192 + 192*768];

__device__ __forceinline__ int gather_row(int m) {
    int win = m >> 6, n = m & 63;
    int b   = win >> 10, rem = win & 1023;
    int wh  = rem >> 5,  ww  = rem & 31;
    int r   = n >> 3,    c   = n & 7;
    int hs  = (wh * 8 + r + 4) & 255;
    int ws_ = (ww * 8 + c + 4) & 255;
    return (b << 16) | (hs << 8) | ws_;
}

__device__ __forceinline__ unsigned smem_u32(const void* p) {
    return (unsigned)__cvta_generic_to_shared(p);
}

// ---------------- all weights fp32 -> bf16, ONE launch ----------------
#define WQ_SZ  110592
#define WP_SZ  36864
#define W1_SZ  147456
#define W2_SZ  147456
#define WTOT   (WQ_SZ + WP_SZ + W1_SZ + W2_SZ)

__global__ void wconv_all(const float* __restrict__ qkv_w, const float* __restrict__ proj_w,
                          const float* __restrict__ w1,    const float* __restrict__ w2,
                          __nv_bfloat16* __restrict__ out) {
    int i = blockIdx.x * 256 + threadIdx.x;
    if (i >= WTOT) return;
    const float* src; int off;
    if (i < WQ_SZ)                 { src = qkv_w;  off = i; }
    else if (i < WQ_SZ + WP_SZ)    { src = proj_w; off = i - WQ_SZ; }
    else if (i < WQ_SZ + WP_SZ + W1_SZ) { src = w1; off = i - WQ_SZ - WP_SZ; }
    else                           { src = w2;     off = i - WQ_SZ - WP_SZ - W1_SZ; }
    out[i] = __float2bfloat16(src[off]);
}

// ---------------- LayerNorm: one warp per row of 192, bf16 out ----------------
__global__ void ln_kernel(const float* __restrict__ in, const float* __restrict__ g,
                          const float* __restrict__ b, __nv_bfloat16* __restrict__ out, int M) {
    int row  = blockIdx.x * (blockDim.x >> 5) + (threadIdx.x >> 5);
    int lane = threadIdx.x & 31;
    if (row >= M) return;
    const float* rp = in + (size_t)row * CH;
    float v[6];
    float s = 0.f;
#pragma unroll
    for (int i = 0; i < 6; i++) { v[i] = rp[lane + 32 * i]; s += v[i]; }
#pragma unroll
    for (int o = 16; o; o >>= 1) s += __shfl_xor_sync(0xffffffffu, s, o);
    float mean = s * (1.f / 192.f);
    float q = 0.f;
#pragma unroll
    for (int i = 0; i < 6; i++) { float d = v[i] - mean; q += d * d; }
#pragma unroll
    for (int o = 16; o; o >>= 1) q += __shfl_xor_sync(0xffffffffu, q, o);
    float inv = rsqrtf(q * (1.f / 192.f) + 1e-5f);
    __nv_bfloat16* op = out + (size_t)row * CH;
#pragma unroll
    for (int i = 0; i < 6; i++) {
        int col = lane + 32 * i;
        op[col] = __float2bfloat16((v[i] - mean) * inv * g[col] + b[col]);
    }
}

// ---------------- HMMA bf16 GEMM, 128x128 tile, k-step 32, 3-stage cp.async (R3-exact) ----------------
#define KSTEP 32
#define SPAD 40

template<int EPI, bool GATHER>
__global__ void __launch_bounds__(256) gemm_mma(
    const __nv_bfloat16* __restrict__ A, const __nv_bfloat16* __restrict__ W,
    const float* __restrict__ bias, const float* __restrict__ res,
    void* __restrict__ Cout, int K, int N)
{
    __shared__ __nv_bfloat16 As[3][128][SPAD];
    __shared__ __nv_bfloat16 Bs[3][128][SPAD];
    const int m0 = blockIdx.x * 128, n0 = blockIdx.y * 128;
    const int t = threadIdx.x, lane = t & 31, wid = t >> 5;
    const int wm = wid & 1, wn = wid >> 1;

    const int lr = t >> 2;
    const int lch = (t & 3) * 8;
    const int ar0 = GATHER ? gather_row(m0 + lr)      : (m0 + lr);
    const int ar1 = GATHER ? gather_row(m0 + 64 + lr) : (m0 + 64 + lr);
    const __nv_bfloat16* Ap0 = A + (size_t)ar0 * K + lch;
    const __nv_bfloat16* Ap1 = A + (size_t)ar1 * K + lch;
    int bg0 = n0 + lr;      if (bg0 >= N) bg0 = 0;
    int bg1 = n0 + 64 + lr; if (bg1 >= N) bg1 = 0;
    const __nv_bfloat16* Wp0 = W + (size_t)bg0 * K + lch;
    const __nv_bfloat16* Wp1 = W + (size_t)bg1 * K + lch;

    float acc[4][4][4];
#pragma unroll
    for (int i = 0; i < 4; i++)
#pragma unroll
        for (int j = 0; j < 4; j++)
#pragma unroll
            for (int q = 0; q < 4; q++) acc[i][j][q] = 0.f;

    const int nk = K / KSTEP;

#define LOAD_STAGE(st, ks)                                                              \
    do {                                                                                \
        unsigned _a0 = smem_u32(&As[st][lr][lch]);                                      \
        unsigned _a1 = smem_u32(&As[st][64 + lr][lch]);                                 \
        unsigned _b0 = smem_u32(&Bs[st][lr][lch]);                                      \
        unsigned _b1 = smem_u32(&Bs[st][64 + lr][lch]);                                 \
        asm volatile("cp.async.cg.shared.global [%0], [%1], 16;\n" :: "r"(_a0), "l"(Ap0 + (ks) * KSTEP)); \
        asm volatile("cp.async.cg.shared.global [%0], [%1], 16;\n" :: "r"(_a1), "l"(Ap1 + (ks) * KSTEP)); \
        asm volatile("cp.async.cg.shared.global [%0], [%1], 16;\n" :: "r"(_b0), "l"(Wp0 + (ks) * KSTEP)); \
        asm volatile("cp.async.cg.shared.global [%0], [%1], 16;\n" :: "r"(_b1), "l"(Wp1 + (ks) * KSTEP)); \
        asm volatile("cp.async.commit_group;\n");                                       \
    } while (0)

    LOAD_STAGE(0, 0);
    LOAD_STAGE(1, 1);

    const int r16 = lane & 15, chh = lane >> 4;

    for (int ks = 0; ks < nk; ks++) {
        if (ks + 1 < nk) asm volatile("cp.async.wait_group 1;\n");
        else             asm volatile("cp.async.wait_group 0;\n");
        __syncthreads();

        if (ks + 2 < nk) {
            int st = (ks + 2) % 3;
            LOAD_STAGE(st, ks + 2);
        }

        const int buf = ks % 3;
#pragma unroll
        for (int kk = 0; kk < 2; kk++) {
            unsigned a[4][4], b[2][4];
#pragma unroll
            for (int i = 0; i < 4; i++) {
                unsigned addr = smem_u32(&As[buf][wm * 64 + i * 16 + r16][kk * 16 + chh * 8]);
                asm volatile("ldmatrix.sync.aligned.m8n8.x4.shared.b16 {%0,%1,%2,%3}, [%4];"
                    : "=r"(a[i][0]), "=r"(a[i][1]), "=r"(a[i][2]), "=r"(a[i][3]) : "r"(addr));
            }
#pragma unroll
            for (int j2 = 0; j2 < 2; j2++) {
                unsigned addr = smem_u32(&Bs[buf][wn * 32 + j2 * 16 + r16][kk * 16 + chh * 8]);
                asm volatile("ldmatrix.sync.aligned.m8n8.x4.shared.b16 {%0,%1,%2,%3}, [%4];"
                    : "=r"(b[j2][0]), "=r"(b[j2][1]), "=r"(b[j2][2]), "=r"(b[j2][3]) : "r"(addr));
            }
#pragma unroll
            for (int i = 0; i < 4; i++)
#pragma unroll
                for (int j = 0; j < 4; j++) {
                    unsigned b0 = b[j >> 1][j & 1], b1 = b[j >> 1][(j & 1) + 2];
                    asm volatile(
                        "mma.sync.aligned.m16n8k16.row.col.f32.bf16.bf16.f32 "
                        "{%0,%1,%2,%3}, {%4,%5,%6,%7}, {%8,%9}, {%0,%1,%2,%3};"
                        : "+f"(acc[i][j][0]), "+f"(acc[i][j][1]), "+f"(acc[i][j][2]), "+f"(acc[i][j][3])
                        : "r"(a[i][0]), "r"(a[i][1]), "r"(a[i][2]), "r"(a[i][3]), "r"(b0), "r"(b1));
                }
        }
    }
#undef LOAD_STAGE

#pragma unroll
    for (int i = 0; i < 4; i++) {
        int rbase = m0 + wm * 64 + i * 16 + (lane >> 2);
#pragma unroll
        for (int j = 0; j < 4; j++) {
            int c = n0 + wn * 32 + j * 8 + (lane & 3) * 2;
            if (c < N) {
#pragma unroll
                for (int h = 0; h < 2; h++) {
                    int r = rbase + h * 8;
                    float v0 = acc[i][j][h * 2 + 0];
                    float v1 = acc[i][j][h * 2 + 1];
                    if (bias) { v0 += __ldg(&bias[c]); v1 += __ldg(&bias[c + 1]); }
                    if (EPI == 1) {
                        v0 = 0.5f * v0 * (1.f + erff(v0 * 0.70710678118654752f));
                        v1 = 0.5f * v1 * (1.f + erff(v1 * 0.70710678118654752f));
                    }
                    if (EPI >= 2) {
                        int orow = (EPI == 2) ? gather_row(r) : r;
                        size_t off = (size_t)orow * N + c;
                        float2 rv = *(const float2*)(res + off);
                        float2 ov; ov.x = v0 + rv.x; ov.y = v1 + rv.y;
                        *(float2*)((float*)Cout + off) = ov;
                    } else {
                        __nv_bfloat162 p;
                        p.x = __float2bfloat16(v0); p.y = __float2bfloat16(v1);
                        *(__nv_bfloat162*)((__nv_bfloat16*)Cout + (size_t)r * N + c) = p;
                    }
                }
            }
        }
    }
}

// ---------------- windowed attention: bf16 smem K/V, scores truly in registers ----------------
__device__ __forceinline__ int region(int p) { return p < 248 ? 0 : (p < 252 ? 1 : 2); }

__global__ void __launch_bounds__(64, 8) attn_kernel(const __nv_bfloat16* __restrict__ qkv,
                                                     const float* __restrict__ rpb,
                                                     __nv_bfloat16* __restrict__ out) {
    __shared__ __nv_bfloat16 skb[64][32];   // K rows, raw bf16
    __shared__ __nv_bfloat16 svb[64][32];   // V rows, raw bf16
    __shared__ float srpb[225];

    const int win = blockIdx.x;
    const int h   = blockIdx.y;
    const int n   = threadIdx.x;

    for (int i = n; i < 225; i += 64) srpb[i] = rpb[i * HEADS + h];

    const size_t base = (size_t)(win * 64 + n) * (3 * CH) + h * 32;
    const float scale = 0.17677669529663687f;

    // raw 16B copies of K and V rows (bit-exact bf16)
    {
        const uint4* kp = (const uint4*)(qkv + base + CH);
        const uint4* vp = (const uint4*)(qkv + base + 2 * CH);
        uint4* kd = (uint4*)skb[n];
        uint4* vd = (uint4*)svb[n];
#pragma unroll
        for (int i = 0; i < 4; i++) { kd[i] = kp[i]; vd[i] = vp[i]; }
    }
    // q -> fp32 regs (scaled)
    float q[32];
    {
        const __nv_bfloat162* qp = (const __nv_bfloat162*)(qkv + base);
#pragma unroll
        for (int i = 0; i < 16; i++) {
            float2 f = __bfloat1622float2(qp[i]);
            q[2 * i] = f.x * scale; q[2 * i + 1] = f.y * scale;
        }
    }
    __syncthreads();

    const int rem = win & 1023;
    const int wh = rem >> 5, ww = rem & 31;
    const int ri = n >> 3, ci = n & 7;
    const int idi = region(wh * 8 + ri) * 3 + region(ww * 8 + ci);

    float s[64];
    float mx = -1e30f;
#pragma unroll 4
    for (int j = 0; j < 64; j++) {
        const uint4* kr = (const uint4*)skb[j];
        float a = 0.f;
#pragma unroll
        for (int m = 0; m < 4; m++) {
            uint4 u = kr[m];
            float2 f0 = __bfloat1622float2(*(__nv_bfloat162*)&u.x);
            float2 f1 = __bfloat1622float2(*(__nv_bfloat162*)&u.y);
            float2 f2 = __bfloat1622float2(*(__nv_bfloat162*)&u.z);
            float2 f3 = __bfloat1622float2(*(__nv_bfloat162*)&u.w);
            int d = m * 8;
            a = fmaf(q[d + 0], f0.x, a); a = fmaf(q[d + 1], f0.y, a);
            a = fmaf(q[d + 2], f1.x, a); a = fmaf(q[d + 3], f1.y, a);
            a = fmaf(q[d + 4], f2.x, a); a = fmaf(q[d + 5], f2.y, a);
            a = fmaf(q[d + 6], f3.x, a); a = fmaf(q[d + 7], f3.y, a);
        }
        int rj = j >> 3, cj = j & 7;
        a += srpb[(ri - rj + 7) * 15 + (ci - cj + 7)];
        int idj = region(wh * 8 + rj) * 3 + region(ww * 8 + cj);
        if (idi != idj) a -= 100.f;
        s[j] = a;
        mx = fmaxf(mx, a);
    }

    float sum = 0.f;
#pragma unroll
    for (int j = 0; j < 64; j++) {
        float e = __expf(s[j] - mx);
        s[j] = e;
        sum += e;
    }
    float inv = 1.f / sum;

    float o[32];
#pragma unroll
    for (int d = 0; d < 32; d++) o[d] = 0.f;
#pragma unroll 4
    for (int j = 0; j < 64; j++) {
        float p = s[j];
        const uint4* vr = (const uint4*)svb[j];
#pragma unroll
        for (int m = 0; m < 4; m++) {
            uint4 u = vr[m];
            float2 f0 = __bfloat1622float2(*(__nv_bfloat162*)&u.x);
            float2 f1 = __bfloat1622float2(*(__nv_bfloat162*)&u.y);
            float2 f2 = __bfloat1622float2(*(__nv_bfloat162*)&u.z);
            float2 f3 = __bfloat1622float2(*(__nv_bfloat162*)&u.w);
            int d = m * 8;
            o[d + 0] = fmaf(p, f0.x, o[d + 0]); o[d + 1] = fmaf(p, f0.y, o[d + 1]);
            o[d + 2] = fmaf(p, f1.x, o[d + 2]); o[d + 3] = fmaf(p, f1.y, o[d + 3]);
            o[d + 4] = fmaf(p, f2.x, o[d + 4]); o[d + 5] = fmaf(p, f2.y, o[d + 5]);
            o[d + 6] = fmaf(p, f3.x, o[d + 6]); o[d + 7] = fmaf(p, f3.y, o[d + 7]);
        }
    }

    __nv_bfloat16* op = out + (size_t)(win * 64 + n) * CH + h * 32;
#pragma unroll
    for (int d2 = 0; d2 < 16; d2++) {
        __nv_bfloat162 p;
        p.x = __float2bfloat16(o[2 * d2] * inv);
        p.y = __float2bfloat16(o[2 * d2 + 1] * inv);
        *(__nv_bfloat162*)&op[2 * d2] = p;
    }
}

// ---------------- launcher ----------------
extern "C" void kernel_launch(void* const* d_in, const int* in_sizes, int n_in,
                              void* d_out, int out_size) {
    const float* x       = (const float*)d_in[0];
    const float* norm1_g = (const float*)d_in[1];
    const float* norm1_b = (const float*)d_in[2];
    const float* qkv_w   = (const float*)d_in[3];
    const float* rpb     = (const float*)d_in[4];
    const float* proj_w  = (const float*)d_in[5];
    const float* proj_b  = (const float*)d_in[6];
    const float* norm2_g = (const float*)d_in[7];
    const float* norm2_b = (const float*)d_in[8];
    const float* mlp_w1  = (const float*)d_in[9];
    const float* mlp_b1  = (const float*)d_in[10];
    const float* mlp_w2  = (const float*)d_in[11];
    const float* mlp_b2  = (const float*)d_in[12];
    float* out = (float*)d_out;

    __nv_bfloat16 *xn, *qkvb, *attnb, *h2, *hid, *wbuf;
    float* x1;
    cudaGetSymbolAddress((void**)&xn,    gb_xn);
    cudaGetSymbolAddress((void**)&qkvb,  gb_qkv);
    cudaGetSymbolAddress((void**)&attnb, gb_attn);
    cudaGetSymbolAddress((void**)&x1,    g_x1);
    cudaGetSymbolAddress((void**)&h2,    gb_h2);
    cudaGetSymbolAddress((void**)&hid,   gb_hid);
    cudaGetSymbolAddress((void**)&wbuf,  gb_w);

    __nv_bfloat16* wq = wbuf;
    __nv_bfloat16* wp = wbuf + WQ_SZ;
    __nv_bfloat16* w1 = wp   + WP_SZ;
    __nv_bfloat16* w2 = w1   + W1_SZ;

    const int M = MTOT;
    const int LN_BLOCKS = M / 8;

    wconv_all<<<(WTOT + 255) / 256, 256>>>(qkv_w, proj_w, mlp_w1, mlp_w2, wbuf);

    ln_kernel<<<LN_BLOCKS, 256>>>(x, norm1_g, norm1_b, xn, M);

    gemm_mma<0, true><<<dim3(M / 128, 5), 256>>>(xn, wq, nullptr, nullptr, qkvb, CH, 3 * CH);

    attn_kernel<<<dim3(2048, HEADS), 64>>>(qkvb, rpb, attnb);

    gemm_mma<2, false><<<dim3(M / 128, 2), 256>>>(attnb, wp, proj_b, x, x1, CH, CH);

    ln_kernel<<<LN_BLOCKS, 256>>>(x1, norm2_g, norm2_b, h2, M);

    gemm_mma<1, false><<<dim3(M / 128, 6), 256>>>(h2, w1, mlp_b1, nullptr, hid, CH, HIDDEN);

    gemm_mma<3, false><<<dim3(M / 128, 2), 256>>>(hid, w2, mlp_b2, x1, out, HIDDEN, CH);
}

// round 9
// speedup vs baseline: 2.0432x; 1.2663x over previous
#include <cuda_runtime.h>
#include <cuda_bf16.h>
#include <math.h>

// ---------------- problem constants ----------------
#define CH 192
#define HEADS 6
#define MTOT 131072
#define HIDDEN 768

// ---------------- scratch ----------------
__device__ __nv_bfloat16 gb_xn  [(size_t)MTOT * CH];
__device__ __nv_bfloat16 gb_qkv [(size_t)MTOT * 3 * CH];
__device__ __nv_bfloat16 gb_attn[(size_t)MTOT * CH];
__device__ float         g_x1   [(size_t)MTOT * CH];
__device__ __nv_bfloat16 gb_h2  [(size_t)MTOT * CH];
__device__ __nv_bfloat16 gb_hid [(size_t)MTOT * HIDDEN];
__device__ __nv_bfloat16 gb_w[576*192 + 192*192 + 768*192 + 192*768];

__device__ __forceinline__ int gather_row(int m) {
    int win = m >> 6, n = m & 63;
    int b   = win >> 10, rem = win & 1023;
    int wh  = rem >> 5,  ww  = rem & 31;
    int r   = n >> 3,    c   = n & 7;
    int hs  = (wh * 8 + r + 4) & 255;
    int ws_ = (ww * 8 + c + 4) & 255;
    return (b << 16) | (hs << 8) | ws_;
}

__device__ __forceinline__ unsigned smem_u32(const void* p) {
    return (unsigned)__cvta_generic_to_shared(p);
}

// ---------------- all weights fp32 -> bf16, ONE launch ----------------
#define WQ_SZ  110592
#define WP_SZ  36864
#define W1_SZ  147456
#define W2_SZ  147456
#define WTOT   (WQ_SZ + WP_SZ + W1_SZ + W2_SZ)

__global__ void wconv_all(const float* __restrict__ qkv_w, const float* __restrict__ proj_w,
                          const float* __restrict__ w1,    const float* __restrict__ w2,
                          __nv_bfloat16* __restrict__ out) {
    int i = blockIdx.x * 256 + threadIdx.x;
    if (i >= WTOT) return;
    const float* src; int off;
    if (i < WQ_SZ)                 { src = qkv_w;  off = i; }
    else if (i < WQ_SZ + WP_SZ)    { src = proj_w; off = i - WQ_SZ; }
    else if (i < WQ_SZ + WP_SZ + W1_SZ) { src = w1; off = i - WQ_SZ - WP_SZ; }
    else                           { src = w2;     off = i - WQ_SZ - WP_SZ - W1_SZ; }
    out[i] = __float2bfloat16(src[off]);
}

// ---------------- LayerNorm: one warp per row of 192, bf16 out ----------------
__global__ void ln_kernel(const float* __restrict__ in, const float* __restrict__ g,
                          const float* __restrict__ b, __nv_bfloat16* __restrict__ out, int M) {
    int row  = blockIdx.x * (blockDim.x >> 5) + (threadIdx.x >> 5);
    int lane = threadIdx.x & 31;
    if (row >= M) return;
    const float* rp = in + (size_t)row * CH;
    float v[6];
    float s = 0.f;
#pragma unroll
    for (int i = 0; i < 6; i++) { v[i] = rp[lane + 32 * i]; s += v[i]; }
#pragma unroll
    for (int o = 16; o; o >>= 1) s += __shfl_xor_sync(0xffffffffu, s, o);
    float mean = s * (1.f / 192.f);
    float q = 0.f;
#pragma unroll
    for (int i = 0; i < 6; i++) { float d = v[i] - mean; q += d * d; }
#pragma unroll
    for (int o = 16; o; o >>= 1) q += __shfl_xor_sync(0xffffffffu, q, o);
    float inv = rsqrtf(q * (1.f / 192.f) + 1e-5f);
    __nv_bfloat16* op = out + (size_t)row * CH;
#pragma unroll
    for (int i = 0; i < 6; i++) {
        int col = lane + 32 * i;
        op[col] = __float2bfloat16((v[i] - mean) * inv * g[col] + b[col]);
    }
}

// ---------------- HMMA bf16 GEMM, 128x128 tile, k-step 32, 3-stage cp.async (R3-exact) ----------------
#define KSTEP 32
#define SPAD 40

template<int EPI, bool GATHER>
__global__ void __launch_bounds__(256) gemm_mma(
    const __nv_bfloat16* __restrict__ A, const __nv_bfloat16* __restrict__ W,
    const float* __restrict__ bias, const float* __restrict__ res,
    void* __restrict__ Cout, int K, int N)
{
    __shared__ __nv_bfloat16 As[3][128][SPAD];
    __shared__ __nv_bfloat16 Bs[3][128][SPAD];
    const int m0 = blockIdx.x * 128, n0 = blockIdx.y * 128;
    const int t = threadIdx.x, lane = t & 31, wid = t >> 5;
    const int wm = wid & 1, wn = wid >> 1;

    const int lr = t >> 2;
    const int lch = (t & 3) * 8;
    const int ar0 = GATHER ? gather_row(m0 + lr)      : (m0 + lr);
    const int ar1 = GATHER ? gather_row(m0 + 64 + lr) : (m0 + 64 + lr);
    const __nv_bfloat16* Ap0 = A + (size_t)ar0 * K + lch;
    const __nv_bfloat16* Ap1 = A + (size_t)ar1 * K + lch;
    int bg0 = n0 + lr;      if (bg0 >= N) bg0 = 0;
    int bg1 = n0 + 64 + lr; if (bg1 >= N) bg1 = 0;
    const __nv_bfloat16* Wp0 = W + (size_t)bg0 * K + lch;
    const __nv_bfloat16* Wp1 = W + (size_t)bg1 * K + lch;

    float acc[4][4][4];
#pragma unroll
    for (int i = 0; i < 4; i++)
#pragma unroll
        for (int j = 0; j < 4; j++)
#pragma unroll
            for (int q = 0; q < 4; q++) acc[i][j][q] = 0.f;

    const int nk = K / KSTEP;

#define LOAD_STAGE(st, ks)                                                              \
    do {                                                                                \
        unsigned _a0 = smem_u32(&As[st][lr][lch]);                                      \
        unsigned _a1 = smem_u32(&As[st][64 + lr][lch]);                                 \
        unsigned _b0 = smem_u32(&Bs[st][lr][lch]);                                      \
        unsigned _b1 = smem_u32(&Bs[st][64 + lr][lch]);                                 \
        asm volatile("cp.async.cg.shared.global [%0], [%1], 16;\n" :: "r"(_a0), "l"(Ap0 + (ks) * KSTEP)); \
        asm volatile("cp.async.cg.shared.global [%0], [%1], 16;\n" :: "r"(_a1), "l"(Ap1 + (ks) * KSTEP)); \
        asm volatile("cp.async.cg.shared.global [%0], [%1], 16;\n" :: "r"(_b0), "l"(Wp0 + (ks) * KSTEP)); \
        asm volatile("cp.async.cg.shared.global [%0], [%1], 16;\n" :: "r"(_b1), "l"(Wp1 + (ks) * KSTEP)); \
        asm volatile("cp.async.commit_group;\n");                                       \
    } while (0)

    LOAD_STAGE(0, 0);
    LOAD_STAGE(1, 1);

    const int r16 = lane & 15, chh = lane >> 4;

    for (int ks = 0; ks < nk; ks++) {
        if (ks + 1 < nk) asm volatile("cp.async.wait_group 1;\n");
        else             asm volatile("cp.async.wait_group 0;\n");
        __syncthreads();

        if (ks + 2 < nk) {
            int st = (ks + 2) % 3;
            LOAD_STAGE(st, ks + 2);
        }

        const int buf = ks % 3;
#pragma unroll
        for (int kk = 0; kk < 2; kk++) {
            unsigned a[4][4], b[2][4];
#pragma unroll
            for (int i = 0; i < 4; i++) {
                unsigned addr = smem_u32(&As[buf][wm * 64 + i * 16 + r16][kk * 16 + chh * 8]);
                asm volatile("ldmatrix.sync.aligned.m8n8.x4.shared.b16 {%0,%1,%2,%3}, [%4];"
                    : "=r"(a[i][0]), "=r"(a[i][1]), "=r"(a[i][2]), "=r"(a[i][3]) : "r"(addr));
            }
#pragma unroll
            for (int j2 = 0; j2 < 2; j2++) {
                unsigned addr = smem_u32(&Bs[buf][wn * 32 + j2 * 16 + r16][kk * 16 + chh * 8]);
                asm volatile("ldmatrix.sync.aligned.m8n8.x4.shared.b16 {%0,%1,%2,%3}, [%4];"
                    : "=r"(b[j2][0]), "=r"(b[j2][1]), "=r"(b[j2][2]), "=r"(b[j2][3]) : "r"(addr));
            }
#pragma unroll
            for (int i = 0; i < 4; i++)
#pragma unroll
                for (int j = 0; j < 4; j++) {
                    unsigned b0 = b[j >> 1][j & 1], b1 = b[j >> 1][(j & 1) + 2];
                    asm volatile(
                        "mma.sync.aligned.m16n8k16.row.col.f32.bf16.bf16.f32 "
                        "{%0,%1,%2,%3}, {%4,%5,%6,%7}, {%8,%9}, {%0,%1,%2,%3};"
                        : "+f"(acc[i][j][0]), "+f"(acc[i][j][1]), "+f"(acc[i][j][2]), "+f"(acc[i][j][3])
                        : "r"(a[i][0]), "r"(a[i][1]), "r"(a[i][2]), "r"(a[i][3]), "r"(b0), "r"(b1));
                }
        }
    }
#undef LOAD_STAGE

#pragma unroll
    for (int i = 0; i < 4; i++) {
        int rbase = m0 + wm * 64 + i * 16 + (lane >> 2);
#pragma unroll
        for (int j = 0; j < 4; j++) {
            int c = n0 + wn * 32 + j * 8 + (lane & 3) * 2;
            if (c < N) {
#pragma unroll
                for (int h = 0; h < 2; h++) {
                    int r = rbase + h * 8;
                    float v0 = acc[i][j][h * 2 + 0];
                    float v1 = acc[i][j][h * 2 + 1];
                    if (bias) { v0 += __ldg(&bias[c]); v1 += __ldg(&bias[c + 1]); }
                    if (EPI == 1) {
                        v0 = 0.5f * v0 * (1.f + erff(v0 * 0.70710678118654752f));
                        v1 = 0.5f * v1 * (1.f + erff(v1 * 0.70710678118654752f));
                    }
                    if (EPI >= 2) {
                        int orow = (EPI == 2) ? gather_row(r) : r;
                        size_t off = (size_t)orow * N + c;
                        float2 rv = *(const float2*)(res + off);
                        float2 ov; ov.x = v0 + rv.x; ov.y = v1 + rv.y;
                        *(float2*)((float*)Cout + off) = ov;
                    } else {
                        __nv_bfloat162 p;
                        p.x = __float2bfloat16(v0); p.y = __float2bfloat16(v1);
                        *(__nv_bfloat162*)((__nv_bfloat16*)Cout + (size_t)r * N + c) = p;
                    }
                }
            }
        }
    }
}

// ---------------- tensor-core windowed attention ----------------
// one block per (window, head); 4 warps, each owns 16 Q rows.
__device__ __forceinline__ int region(int p) { return p < 248 ? 0 : (p < 252 ? 1 : 2); }

__global__ void __launch_bounds__(128) attn_kernel(const __nv_bfloat16* __restrict__ qkv,
                                                   const float* __restrict__ rpb,
                                                   __nv_bfloat16* __restrict__ out) {
    __shared__ __nv_bfloat16 Qs[64][40];
    __shared__ __nv_bfloat16 Ks[64][40];
    __shared__ __nv_bfloat16 Vs[64][40];
    __shared__ float srpb[225];
    __shared__ int   sreg[64];

    const int win = blockIdx.x, h = blockIdx.y;
    const int t = threadIdx.x, lane = t & 31, warp = t >> 5;
    const float scale = 0.17677669529663687f;   // 1/sqrt(32)

    for (int i = t; i < 225; i += 128) srpb[i] = rpb[i * HEADS + h];
    if (t < 64) {
        int rem = win & 1023;
        int wh = rem >> 5, ww = rem & 31;
        sreg[t] = region(wh * 8 + (t >> 3)) * 3 + region(ww * 8 + (t & 7));
    }
#pragma unroll
    for (int it = 0; it < 2; it++) {
        int c = t + it * 128;                 // 0..255 : 64 rows x 4 chunks
        int row = c >> 2, off = (c & 3) * 8;
        const __nv_bfloat16* src = qkv + (size_t)(win * 64 + row) * 576 + h * 32 + off;
        *(uint4*)&Qs[row][off] = *(const uint4*)(src);
        *(uint4*)&Ks[row][off] = *(const uint4*)(src + 192);
        *(uint4*)&Vs[row][off] = *(const uint4*)(src + 384);
    }
    __syncthreads();

    // ---- fragments: Q (A-operand), K (B-operand) -- identical recipe to gemm_mma
    unsigned qa[2][4], kb[4][2][4];
    const int r16 = lane & 15, chh = lane >> 4;
#pragma unroll
    for (int kt = 0; kt < 2; kt++) {
        unsigned addr = smem_u32(&Qs[warp * 16 + r16][chh * 8 + kt * 16]);
        asm volatile("ldmatrix.sync.aligned.m8n8.x4.shared.b16 {%0,%1,%2,%3}, [%4];"
            : "=r"(qa[kt][0]), "=r"(qa[kt][1]), "=r"(qa[kt][2]), "=r"(qa[kt][3]) : "r"(addr));
    }
#pragma unroll
    for (int j2 = 0; j2 < 4; j2++)
#pragma unroll
        for (int kt = 0; kt < 2; kt++) {
            unsigned addr = smem_u32(&Ks[j2 * 16 + r16][chh * 8 + kt * 16]);
            asm volatile("ldmatrix.sync.aligned.m8n8.x4.shared.b16 {%0,%1,%2,%3}, [%4];"
                : "=r"(kb[j2][kt][0]), "=r"(kb[j2][kt][1]), "=r"(kb[j2][kt][2]), "=r"(kb[j2][kt][3]) : "r"(addr));
        }

    // ---- S = Q K^T  (16x64 per warp, fp32 frags)
    float s[8][4];
#pragma unroll
    for (int nt = 0; nt < 8; nt++) {
        s[nt][0] = s[nt][1] = s[nt][2] = s[nt][3] = 0.f;
#pragma unroll
        for (int kt = 0; kt < 2; kt++) {
            unsigned b0 = kb[nt >> 1][kt][nt & 1], b1 = kb[nt >> 1][kt][(nt & 1) + 2];
            asm volatile(
                "mma.sync.aligned.m16n8k16.row.col.f32.bf16.bf16.f32 "
                "{%0,%1,%2,%3}, {%4,%5,%6,%7}, {%8,%9}, {%0,%1,%2,%3};"
                : "+f"(s[nt][0]), "+f"(s[nt][1]), "+f"(s[nt][2]), "+f"(s[nt][3])
                : "r"(qa[0][0]), "r"(qa[0][1]), "r"(qa[0][2]), "r"(qa[0][3]), "r"(b0), "r"(b1));
            (void)kt;
            if (kt == 0) { b0 = kb[nt >> 1][1][nt & 1]; b1 = kb[nt >> 1][1][(nt & 1) + 2];
                asm volatile(
                    "mma.sync.aligned.m16n8k16.row.col.f32.bf16.bf16.f32 "
                    "{%0,%1,%2,%3}, {%4,%5,%6,%7}, {%8,%9}, {%0,%1,%2,%3};"
                    : "+f"(s[nt][0]), "+f"(s[nt][1]), "+f"(s[nt][2]), "+f"(s[nt][3])
                    : "r"(qa[1][0]), "r"(qa[1][1]), "r"(qa[1][2]), "r"(qa[1][3]), "r"(b0), "r"(b1));
                break; }
        }
    }

    // ---- scale + bias + mask on fragment
    const int qi0 = warp * 16 + (lane >> 2);
    const int qi1 = qi0 + 8;
    const int ri0 = qi0 >> 3, ci0 = qi0 & 7;
    const int ri1 = qi1 >> 3, ci1 = qi1 & 7;
    const int id0 = sreg[qi0], id1 = sreg[qi1];

    float mx0 = -1e30f, mx1 = -1e30f;
#pragma unroll
    for (int nt = 0; nt < 8; nt++) {
#pragma unroll
        for (int e = 0; e < 2; e++) {
            int j = nt * 8 + (lane & 3) * 2 + e;
            int rj = j >> 3, cj = j & 7, idj = sreg[j];
            float f0 = s[nt][e]     * scale + srpb[(ri0 - rj + 7) * 15 + (ci0 - cj + 7)];
            float f1 = s[nt][e + 2] * scale + srpb[(ri1 - rj + 7) * 15 + (ci1 - cj + 7)];
            if (id0 != idj) f0 -= 100.f;
            if (id1 != idj) f1 -= 100.f;
            s[nt][e] = f0; s[nt][e + 2] = f1;
            mx0 = fmaxf(mx0, f0); mx1 = fmaxf(mx1, f1);
        }
    }
    mx0 = fmaxf(mx0, __shfl_xor_sync(0xffffffffu, mx0, 1));
    mx0 = fmaxf(mx0, __shfl_xor_sync(0xffffffffu, mx0, 2));
    mx1 = fmaxf(mx1, __shfl_xor_sync(0xffffffffu, mx1, 1));
    mx1 = fmaxf(mx1, __shfl_xor_sync(0xffffffffu, mx1, 2));

    float sum0 = 0.f, sum1 = 0.f;
#pragma unroll
    for (int nt = 0; nt < 8; nt++) {
#pragma unroll
        for (int e = 0; e < 2; e++) {
            float e0 = __expf(s[nt][e]     - mx0);
            float e1 = __expf(s[nt][e + 2] - mx1);
            s[nt][e] = e0; s[nt][e + 2] = e1;
            sum0 += e0; sum1 += e1;
        }
    }
    sum0 += __shfl_xor_sync(0xffffffffu, sum0, 1);
    sum0 += __shfl_xor_sync(0xffffffffu, sum0, 2);
    sum1 += __shfl_xor_sync(0xffffffffu, sum1, 1);
    sum1 += __shfl_xor_sync(0xffffffffu, sum1, 2);
    float inv0 = 1.f / sum0, inv1 = 1.f / sum1;

    // ---- P (C-frag) -> A-frag bf16
    unsigned pa[4][4];
#pragma unroll
    for (int kt = 0; kt < 4; kt++) {
        __nv_bfloat162 p;
        p = __floats2bfloat162_rn(s[2 * kt][0],     s[2 * kt][1]);     pa[kt][0] = *(unsigned*)&p;
        p = __floats2bfloat162_rn(s[2 * kt][2],     s[2 * kt][3]);     pa[kt][1] = *(unsigned*)&p;
        p = __floats2bfloat162_rn(s[2 * kt + 1][0], s[2 * kt + 1][1]); pa[kt][2] = *(unsigned*)&p;
        p = __floats2bfloat162_rn(s[2 * kt + 1][2], s[2 * kt + 1][3]); pa[kt][3] = *(unsigned*)&p;
    }

    // ---- O = P V  (V B-frags via ldmatrix.x2.trans from [j][d] rows)
    float o[4][4];
#pragma unroll
    for (int nt = 0; nt < 4; nt++) o[nt][0] = o[nt][1] = o[nt][2] = o[nt][3] = 0.f;
#pragma unroll
    for (int kt = 0; kt < 4; kt++) {
#pragma unroll
        for (int nt = 0; nt < 4; nt++) {
            unsigned addr = smem_u32(&Vs[kt * 16 + r16][nt * 8]);
            unsigned b0, b1;
            asm volatile("ldmatrix.sync.aligned.m8n8.x2.trans.shared.b16 {%0,%1}, [%2];"
                : "=r"(b0), "=r"(b1) : "r"(addr));
            asm volatile(
                "mma.sync.aligned.m16n8k16.row.col.f32.bf16.bf16.f32 "
                "{%0,%1,%2,%3}, {%4,%5,%6,%7}, {%8,%9}, {%0,%1,%2,%3};"
                : "+f"(o[nt][0]), "+f"(o[nt][1]), "+f"(o[nt][2]), "+f"(o[nt][3])
                : "r"(pa[kt][0]), "r"(pa[kt][1]), "r"(pa[kt][2]), "r"(pa[kt][3]), "r"(b0), "r"(b1));
        }
    }

    // ---- store (deferred softmax normalization)
    __nv_bfloat16* op = out + (size_t)(win * 64) * CH + h * 32;
#pragma unroll
    for (int nt = 0; nt < 4; nt++) {
        int col = nt * 8 + (lane & 3) * 2;
        __nv_bfloat162 p0 = __floats2bfloat162_rn(o[nt][0] * inv0, o[nt][1] * inv0);
        __nv_bfloat162 p1 = __floats2bfloat162_rn(o[nt][2] * inv1, o[nt][3] * inv1);
        *(__nv_bfloat162*)&op[(size_t)qi0 * CH + col] = p0;
        *(__nv_bfloat162*)&op[(size_t)qi1 * CH + col] = p1;
    }
}

// ---------------- launcher ----------------
extern "C" void kernel_launch(void* const* d_in, const int* in_sizes, int n_in,
                              void* d_out, int out_size) {
    const float* x       = (const float*)d_in[0];
    const float* norm1_g = (const float*)d_in[1];
    const float* norm1_b = (const float*)d_in[2];
    const float* qkv_w   = (const float*)d_in[3];
    const float* rpb     = (const float*)d_in[4];
    const float* proj_w  = (const float*)d_in[5];
    const float* proj_b  = (const float*)d_in[6];
    const float* norm2_g = (const float*)d_in[7];
    const float* norm2_b = (const float*)d_in[8];
    const float* mlp_w1  = (const float*)d_in[9];
    const float* mlp_b1  = (const float*)d_in[10];
    const float* mlp_w2  = (const float*)d_in[11];
    const float* mlp_b2  = (const float*)d_in[12];
    float* out = (float*)d_out;

    __nv_bfloat16 *xn, *qkvb, *attnb, *h2, *hid, *wbuf;
    float* x1;
    cudaGetSymbolAddress((void**)&xn,    gb_xn);
    cudaGetSymbolAddress((void**)&qkvb,  gb_qkv);
    cudaGetSymbolAddress((void**)&attnb, gb_attn);
    cudaGetSymbolAddress((void**)&x1,    g_x1);
    cudaGetSymbolAddress((void**)&h2,    gb_h2);
    cudaGetSymbolAddress((void**)&hid,   gb_hid);
    cudaGetSymbolAddress((void**)&wbuf,  gb_w);

    __nv_bfloat16* wq = wbuf;
    __nv_bfloat16* wp = wbuf + WQ_SZ;
    __nv_bfloat16* w1 = wp   + WP_SZ;
    __nv_bfloat16* w2 = w1   + W1_SZ;

    const int M = MTOT;
    const int LN_BLOCKS = M / 8;

    wconv_all<<<(WTOT + 255) / 256, 256>>>(qkv_w, proj_w, mlp_w1, mlp_w2, wbuf);

    ln_kernel<<<LN_BLOCKS, 256>>>(x, norm1_g, norm1_b, xn, M);

    gemm_mma<0, true><<<dim3(M / 128, 5), 256>>>(xn, wq, nullptr, nullptr, qkvb, CH, 3 * CH);

    attn_kernel<<<dim3(2048, HEADS), 128>>>(qkvb, rpb, attnb);

    gemm_mma<2, false><<<dim3(M / 128, 2), 256>>>(attnb, wp, proj_b, x, x1, CH, CH);

    ln_kernel<<<LN_BLOCKS, 256>>>(x1, norm2_g, norm2_b, h2, M);

    gemm_mma<1, false><<<dim3(M / 128, 6), 256>>>(h2, w1, mlp_b1, nullptr, hid, CH, HIDDEN);

    gemm_mma<3, false><<<dim3(M / 128, 2), 256>>>(hid, w2, mlp_b2, x1, out, HIDDEN, CH);
}